// round 14
// baseline (speedup 1.0000x reference)
#include <cuda_runtime.h>
#include <cuda_fp16.h>
#include <cstdint>

// Problem constants
#define NV      8000
#define NVP     8064          // padded to multiple of BN=128 (63 n-blocks)
#define NVT     20000
#define BATCH   8
#define CSUM    960

// GEMM tiling (fp16 mma.sync, BK=64) — R10 config (best known mainloop)
#define BM 128
#define BN 128
#define BK 64
#define NTHREADS 256
#define NSTG 3
#define A_ST 16384
#define B_ST 16384
#define STG_BYTES (A_ST + B_ST)            // 32768
#define SMEM_BYTES (NSTG * STG_BYTES)      // 98304

#define SWB(r, ck) ((unsigned)((r) * 128 + ((((ck) ^ ((r) & 7))) << 4)))

// Layer-0 N-chunking: 3 chunks of 21 n-blocks (2688 cols)
#define NCHUNK 2688

// Per-layer panel offsets; K_pads = {3136, 832, 256, 64}
#define A_TOT (512*3136 + 1024*832 + 2048*256 + 4096*64)
#define B_TOT ((size_t)NVP * (3136 + 832 + 256 + 64))

// Scratch (device globals: allowed, no runtime allocation)
__device__ int    g_idx32[NV];
__device__ float  g_wsel[CSUM * NV];
__device__ __half g_Ah[A_TOT];
__device__ __half g_Bh[B_TOT];

__device__ __forceinline__ uint32_t smem_u32(const void* p) {
    uint32_t a;
    asm("{ .reg .u64 t; cvta.to.shared.u64 t, %1; cvt.u32.u64 %0, t; }" : "=r"(a) : "l"(p));
    return a;
}

// ---------------------------------------------------------------------------
// roi dtype sniff: reference asks int64, but JAX (x64 off) materializes int32.
// ---------------------------------------------------------------------------
__device__ __forceinline__ int load_roi(const void* roi, int n) {
    const int* ri = (const int*)roi;
    bool is64 = (ri[1] == 0) & (ri[7] == 0) & (ri[4001] == 0) & (ri[7999] == 0);
    return is64 ? (int)((const long long*)roi)[n] : ri[n];
}

// Prep 0: indices only (unblocks B gather immediately). grid=(32),256.
__global__ __launch_bounds__(256) void prep_idx_kernel(const void* __restrict__ roi)
{
    int n = blockIdx.x * 256 + threadIdx.x;
    if (n < NV) g_idx32[n] = load_roi(roi, n);
}

// Prep 1: w gather (uses g_idx32). grid=(32,240), 4 rows/block.
__global__ __launch_bounds__(256) void prep_w_kernel(
    const float* __restrict__ w0, const float* __restrict__ w1,
    const float* __restrict__ w2, const float* __restrict__ w3)
{
    int n = blockIdx.x * 256 + threadIdx.x;
    if (n >= NV) return;
    int idx = g_idx32[n];
    #pragma unroll
    for (int rr = 0; rr < 4; rr++) {
        int row = blockIdx.y * 4 + rr;
        const float* w; int c;
        if (row < 64)       { w = w0; c = row;        }
        else if (row < 192) { w = w1; c = row - 64;   }
        else if (row < 448) { w = w2; c = row - 192;  }
        else                { w = w3; c = row - 448;  }
        g_wsel[(size_t)row * NV + n] = w[(size_t)c * NVT + idx];
    }
}

// Prep 2: A -> fp16, [M][K_pad] at aOff, zero-padded.
__global__ __launch_bounds__(256) void prep_a_kernel(
    const float* __restrict__ A, int M, int K, int K_pad, int aOff)
{
    int base = (blockIdx.x * 256 + threadIdx.x) * 4;
    #pragma unroll
    for (int j = 0; j < 4; j++) {
        int e = base + j;
        if (e >= M * K_pad) return;
        int r = e / K_pad, k = e - r * K_pad;
        g_Ah[aOff + e] = (k < K) ? __float2half_rn(A[(size_t)r * K + k])
                                 : __float2half_rn(0.f);
    }
}

// Prep 3: B panel [n][K_pad] fp16 at bOff, n in [nBase, nBase+64*gridDim.x).
// Block: 64 n x 32 k, smem transpose.
__global__ __launch_bounds__(256) void prep_b_kernel(
    const float* __restrict__ RF, int K, int K_pad, size_t bOff, int nBase)
{
    __shared__ float s[64][33];
    int t  = threadIdx.x;
    int n0 = nBase + blockIdx.x * 64;
    int k0 = blockIdx.y * 32;

    int n_l = t & 63;
    int kq  = t >> 6;
    int n   = n0 + n_l;
    int idx = (n < NV) ? g_idx32[n] : 0;
    #pragma unroll
    for (int p = 0; p < 8; p++) {
        int k_l = p * 4 + kq;
        int k   = k0 + k_l;
        float v = 0.f;
        if (k < K && n < NV) {
            float x = RF[(size_t)k * NVT + idx];
            v = (x > 0.f) ? x : 0.01f * x;
        }
        s[n_l][k_l] = v;
    }
    __syncthreads();

    int nr = t >> 2;
    int q  = t & 3;
    __half h[8];
    #pragma unroll
    for (int i = 0; i < 8; i++) h[i] = __float2half_rn(s[nr][q * 8 + i]);
    *(uint4*)&g_Bh[bOff + (size_t)(n0 + nr) * K_pad + k0 + q * 8] = *(uint4*)h;
}

// ---------------------------------------------------------------------------
// FP16 GEMM (f32 accumulate), BK=64, 3-stage cp.async, ldmatrix fragments,
// w-scale epilogue. Panels at aOff/bOff; n-range starts at nBase.
// block = 256 (8 warps: 2M x 4N, warp tile 64x32).
// ---------------------------------------------------------------------------
__global__ __launch_bounds__(NTHREADS, 2) void gemm_fp16_kernel(
    float* __restrict__ out, int K_pad, int cShift, int off, int aOff,
    size_t bOff, int nBase)
{
    extern __shared__ __align__(128) char smem[];
    const uint32_t smb = smem_u32(smem);

    const int tid  = threadIdx.x;
    const int m0   = blockIdx.x * BM;
    const int n0   = nBase + blockIdx.y * BN;
    const int lane = tid & 31;
    const int warp = tid >> 5;
    const int g    = lane >> 2;
    const int t    = lane & 3;
    const int warpM = warp >> 2;
    const int warpN = warp & 3;
    const int niter = K_pad / BK;

    const __half* __restrict__ Ap = g_Ah + aOff;
    const __half* __restrict__ Bp = g_Bh + bOff;

    float acc[4][4][4];
    #pragma unroll
    for (int i = 0; i < 4; i++)
        #pragma unroll
        for (int j = 0; j < 4; j++)
            #pragma unroll
            for (int r = 0; r < 4; r++) acc[i][j][r] = 0.f;

    auto issue = [&](int j) {
        uint32_t Ab = smb + (j % NSTG) * STG_BYTES;
        uint32_t Bb = Ab + A_ST;
        int k0 = j * BK;
        #pragma unroll
        for (int u = 0; u < 4; u++) {
            int e = tid + NTHREADS * u;
            int r = e >> 3, ck = e & 7;
            const __half* srcA = Ap + (size_t)(m0 + r) * K_pad + k0 + ck * 8;
            asm volatile("cp.async.cg.shared.global [%0], [%1], 16;"
                         :: "r"(Ab + SWB(r, ck)), "l"(srcA));
            const __half* srcB = Bp + (size_t)(n0 + r) * K_pad + k0 + ck * 8;
            asm volatile("cp.async.cg.shared.global [%0], [%1], 16;"
                         :: "r"(Bb + SWB(r, ck)), "l"(srcB));
        }
    };

    #pragma unroll
    for (int p = 0; p < NSTG - 1; p++) {
        if (p < niter) issue(p);
        asm volatile("cp.async.commit_group;");
    }

    const int la_row8 = (lane & 7) + ((lane >> 3) & 1) * 8;
    const int la_ckhi = lane >> 4;
    const int lb_row  = (lane & 7) + ((lane >> 4) << 3);
    const int lb_ck   = (lane >> 3) & 1;

    for (int i = 0; i < niter; i++) {
        asm volatile("cp.async.wait_group %0;" :: "n"(NSTG - 2));
        __syncthreads();
        if (i + NSTG - 1 < niter) issue(i + NSTG - 1);
        asm volatile("cp.async.commit_group;");

        uint32_t As = smb + (i % NSTG) * STG_BYTES;
        uint32_t Bs = As + A_ST;

        #pragma unroll
        for (int s = 0; s < 4; s++) {
            uint32_t a[4][4];
            #pragma unroll
            for (int mf = 0; mf < 4; mf++) {
                int row = warpM * 64 + mf * 16 + la_row8;
                int ck  = s * 2 + la_ckhi;
                uint32_t ad = As + SWB(row, ck);
                asm volatile("ldmatrix.sync.aligned.m8n8.x4.shared.b16 "
                             "{%0,%1,%2,%3}, [%4];"
                             : "=r"(a[mf][0]), "=r"(a[mf][1]),
                               "=r"(a[mf][2]), "=r"(a[mf][3]) : "r"(ad));
            }
            uint32_t b[4][2];
            #pragma unroll
            for (int nfp = 0; nfp < 2; nfp++) {
                int row = warpN * 32 + nfp * 16 + lb_row;
                int ck  = s * 2 + lb_ck;
                uint32_t bd = Bs + SWB(row, ck);
                uint32_t r0, r1, r2, r3;
                asm volatile("ldmatrix.sync.aligned.m8n8.x4.shared.b16 "
                             "{%0,%1,%2,%3}, [%4];"
                             : "=r"(r0), "=r"(r1), "=r"(r2), "=r"(r3) : "r"(bd));
                b[nfp * 2 + 0][0] = r0; b[nfp * 2 + 0][1] = r1;
                b[nfp * 2 + 1][0] = r2; b[nfp * 2 + 1][1] = r3;
            }
            #pragma unroll
            for (int mf = 0; mf < 4; mf++)
                #pragma unroll
                for (int nf = 0; nf < 4; nf++) {
                    asm volatile(
                        "mma.sync.aligned.m16n8k16.row.col.f32.f16.f16.f32 "
                        "{%0,%1,%2,%3}, {%4,%5,%6,%7}, {%8,%9}, {%0,%1,%2,%3};"
                        : "+f"(acc[mf][nf][0]), "+f"(acc[mf][nf][1]),
                          "+f"(acc[mf][nf][2]), "+f"(acc[mf][nf][3])
                        : "r"(a[mf][0]), "r"(a[mf][1]), "r"(a[mf][2]), "r"(a[mf][3]),
                          "r"(b[nf][0]), "r"(b[nf][1]));
                }
        }
        __syncthreads();
    }

    const int cMask = (1 << cShift) - 1;
    #pragma unroll
    for (int mf = 0; mf < 4; mf++) {
        #pragma unroll
        for (int half = 0; half < 2; half++) {
            int m   = m0 + warpM * 64 + mf * 16 + g + half * 8;
            int c   = m & cMask;
            int bI  = m >> cShift;
            const float* wrow = g_wsel + (size_t)(off + c) * NV;
            float* orow = out + ((size_t)bI * CSUM + off + c) * NV;
            #pragma unroll
            for (int nf = 0; nf < 4; nf++) {
                int n = n0 + warpN * 32 + nf * 8 + t * 2;
                if (n < NV) {
                    float2 wv = *(const float2*)(wrow + n);
                    float2 res;
                    res.x = acc[mf][nf][half * 2 + 0] * wv.x;
                    res.y = acc[mf][nf][half * 2 + 1] * wv.y;
                    *(float2*)(orow + n) = res;
                }
            }
        }
    }
}

// ---------------------------------------------------------------------------
// Streams + events, created once pre-main. Fallback: fully sequential.
// ---------------------------------------------------------------------------
struct OverlapCtx {
    cudaStream_t s1 = nullptr, s2 = nullptr;
    cudaEvent_t evI = nullptr, evW = nullptr, evS2 = nullptr;
    cudaEvent_t evB0[3] = {nullptr, nullptr, nullptr};
    cudaEvent_t evL[3] = {nullptr, nullptr, nullptr};   // layers 1-3 B done
    bool ok = false;
    OverlapCtx() {
        bool o = (cudaStreamCreateWithFlags(&s1, cudaStreamNonBlocking) == cudaSuccess)
              && (cudaStreamCreateWithFlags(&s2, cudaStreamNonBlocking) == cudaSuccess)
              && (cudaEventCreateWithFlags(&evI, cudaEventDisableTiming) == cudaSuccess)
              && (cudaEventCreateWithFlags(&evW, cudaEventDisableTiming) == cudaSuccess)
              && (cudaEventCreateWithFlags(&evS2, cudaEventDisableTiming) == cudaSuccess);
        for (int i = 0; i < 3 && o; i++)
            o = (cudaEventCreateWithFlags(&evB0[i], cudaEventDisableTiming) == cudaSuccess)
             && (cudaEventCreateWithFlags(&evL[i], cudaEventDisableTiming) == cudaSuccess);
        ok = o;
    }
};
static OverlapCtx g_ctx;

// ---------------------------------------------------------------------------
extern "C" void kernel_launch(void* const* d_in, const int* in_sizes, int n_in,
                              void* d_out, int out_size)
{
    static const int fsz[4] = {1605632,  802816,  401408,  200704};
    static const int rsz[4] = {62720000, 15680000, 3920000, 980000};
    static const int wsz[4] = {1280000,  2560000,  5120000, 10240000};

    const float* F[4]  = {nullptr, nullptr, nullptr, nullptr};
    const float* RF[4] = {nullptr, nullptr, nullptr, nullptr};
    const float* W[4]  = {nullptr, nullptr, nullptr, nullptr};
    const void* roi = nullptr;

    for (int i = 0; i < n_in; i++) {
        int s = in_sizes[i];
        if (s == NV) { roi = d_in[i]; continue; }
        for (int j = 0; j < 4; j++) {
            if (s == fsz[j]) F[j]  = (const float*)d_in[i];
            if (s == rsz[j]) RF[j] = (const float*)d_in[i];
            if (s == wsz[j]) W[j]  = (const float*)d_in[i];
        }
    }

    float* out = (float*)d_out;

    static bool attr_set = false;
    if (!attr_set) {
        cudaFuncSetAttribute(gemm_fp16_kernel,
                             cudaFuncAttributeMaxDynamicSharedMemorySize, SMEM_BYTES);
        attr_set = true;
    }

    static const int Cs[4]    = {64, 128, 256, 512};
    static const int cSh[4]   = {6, 7, 8, 9};
    static const int Ks[4]    = {3136, 784, 196, 49};
    static const int Kpads[4] = {3136, 832, 256, 64};
    static const int offs[4]  = {0, 64, 192, 448};
    static const int aOff[4]  = {0, 512*3136, 512*3136 + 1024*832,
                                 512*3136 + 1024*832 + 2048*256};
    static const size_t bOff[4] = {0, (size_t)NVP*3136, (size_t)NVP*(3136+832),
                                   (size_t)NVP*(3136+832+256)};

    auto prepA = [&](int l, cudaStream_t st) {
        int M = BATCH * Cs[l];
        prep_a_kernel<<<(M * Kpads[l] + 1023) / 1024, 256, 0, st>>>(
            F[l], M, Ks[l], Kpads[l], aOff[l]);
    };
    auto prepB = [&](int l, cudaStream_t st, int nBase, int nCols) {
        prep_b_kernel<<<dim3(nCols / 64, Kpads[l] / 32), 256, 0, st>>>(
            RF[l], Ks[l], Kpads[l], bOff[l], nBase);
    };
    auto gemm = [&](int l, int nBase, int nCols) {
        int M = BATCH * Cs[l];
        dim3 grid(M / BM, nCols / BN);
        gemm_fp16_kernel<<<grid, NTHREADS, SMEM_BYTES>>>(
            out, Kpads[l], cSh[l], offs[l], aOff[l], bOff[l], nBase);
    };

    if (g_ctx.ok) {
        // s0: idx -> (fork) -> prep_a0 -> gemm0 chunks -> gemm1-3
        prep_idx_kernel<<<32, 256>>>(roi);
        cudaEventRecord(g_ctx.evI, 0);
        cudaStreamWaitEvent(g_ctx.s1, g_ctx.evI, 0);
        cudaStreamWaitEvent(g_ctx.s2, g_ctx.evI, 0);

        // s1: B0 chunks, then B+... for layers 1-3
        for (int c = 0; c < 3; c++) {
            prepB(0, g_ctx.s1, c * NCHUNK, NCHUNK);
            cudaEventRecord(g_ctx.evB0[c], g_ctx.s1);
        }
        for (int l = 1; l < 4; l++) {
            prepB(l, g_ctx.s1, 0, NVP);
            cudaEventRecord(g_ctx.evL[l - 1], g_ctx.s1);
        }

        // s2: w gather + A panels for layers 1-3
        prep_w_kernel<<<dim3(32, 240), 256, 0, g_ctx.s2>>>(W[0], W[1], W[2], W[3]);
        cudaEventRecord(g_ctx.evW, g_ctx.s2);
        prepA(1, g_ctx.s2); prepA(2, g_ctx.s2); prepA(3, g_ctx.s2);
        cudaEventRecord(g_ctx.evS2, g_ctx.s2);

        // s0 main chain
        prepA(0, 0);
        cudaStreamWaitEvent(0, g_ctx.evW, 0);     // epilogue needs wsel
        for (int c = 0; c < 3; c++) {
            cudaStreamWaitEvent(0, g_ctx.evB0[c], 0);
            gemm(0, c * NCHUNK, NCHUNK);
        }
        cudaStreamWaitEvent(0, g_ctx.evS2, 0);    // A1-3 ready
        for (int l = 1; l < 4; l++) {
            cudaStreamWaitEvent(0, g_ctx.evL[l - 1], 0);
            gemm(l, 0, NVP);
        }
    } else {
        prep_idx_kernel<<<32, 256>>>(roi);
        prep_w_kernel<<<dim3(32, 240), 256>>>(W[0], W[1], W[2], W[3]);
        for (int l = 0; l < 4; l++) {
            prepA(l, 0);
            prepB(l, 0, 0, NVP);
            gemm(l, 0, NVP);
        }
    }
}

// round 16
// speedup vs baseline: 1.2277x; 1.2277x over previous
#include <cuda_runtime.h>
#include <cuda_fp16.h>
#include <cstdint>

// Problem constants
#define NV      8000
#define NVP     8064          // padded to multiple of BN=128 (63 n-blocks)
#define NVT     20000
#define BATCH   8
#define CSUM    960

// GEMM tiling (fp16 mma.sync, BK=64) — R10 config (best known mainloop)
#define BM 128
#define BN 128
#define BK 64
#define NTHREADS 256
#define NSTG 3
#define A_ST 16384
#define B_ST 16384
#define STG_BYTES (A_ST + B_ST)            // 32768
#define SMEM_BYTES (NSTG * STG_BYTES)      // 98304

#define SWB(r, ck) ((unsigned)((r) * 128 + ((((ck) ^ ((r) & 7))) << 4)))

// Per-layer panel offsets; K_pads = {3136, 832, 256, 64}
#define A_TOT (512*3136 + 1024*832 + 2048*256 + 4096*64)
#define B_TOT ((size_t)NVP * (3136 + 832 + 256 + 64))

// Scratch (device globals: allowed, no runtime allocation)
__device__ int    g_idx32[NV];
__device__ float  g_wsel[CSUM * NV];
__device__ __half g_Ah[A_TOT];
__device__ __half g_Bh[B_TOT];

__device__ __forceinline__ uint32_t smem_u32(const void* p) {
    uint32_t a;
    asm("{ .reg .u64 t; cvta.to.shared.u64 t, %1; cvt.u32.u64 %0, t; }" : "=r"(a) : "l"(p));
    return a;
}

// ---------------------------------------------------------------------------
// roi dtype sniff: reference asks int64, but JAX (x64 off) materializes int32.
// ---------------------------------------------------------------------------
__device__ __forceinline__ int load_roi(const void* roi, int n) {
    const int* ri = (const int*)roi;
    bool is64 = (ri[1] == 0) & (ri[7] == 0) & (ri[4001] == 0) & (ri[7999] == 0);
    return is64 ? (int)((const long long*)roi)[n] : ri[n];
}

// Prep 0: indices only. grid=(32),256.
__global__ __launch_bounds__(256) void prep_idx_kernel(const void* __restrict__ roi)
{
    int n = blockIdx.x * 256 + threadIdx.x;
    if (n < NV) g_idx32[n] = load_roi(roi, n);
}

// Prep 1: w gather (uses g_idx32). grid=(32,240), 4 rows/block.
__global__ __launch_bounds__(256) void prep_w_kernel(
    const float* __restrict__ w0, const float* __restrict__ w1,
    const float* __restrict__ w2, const float* __restrict__ w3)
{
    int n = blockIdx.x * 256 + threadIdx.x;
    if (n >= NV) return;
    int idx = g_idx32[n];
    #pragma unroll
    for (int rr = 0; rr < 4; rr++) {
        int row = blockIdx.y * 4 + rr;
        const float* w; int c;
        if (row < 64)       { w = w0; c = row;        }
        else if (row < 192) { w = w1; c = row - 64;   }
        else if (row < 448) { w = w2; c = row - 192;  }
        else                { w = w3; c = row - 448;  }
        g_wsel[(size_t)row * NV + n] = w[(size_t)c * NVT + idx];
    }
}

// Prep 2: A -> fp16, [M][K_pad] at aOff, zero-padded.
__global__ __launch_bounds__(256) void prep_a_kernel(
    const float* __restrict__ A, int M, int K, int K_pad, int aOff)
{
    int base = (blockIdx.x * 256 + threadIdx.x) * 4;
    #pragma unroll
    for (int j = 0; j < 4; j++) {
        int e = base + j;
        if (e >= M * K_pad) return;
        int r = e / K_pad, k = e - r * K_pad;
        g_Ah[aOff + e] = (k < K) ? __float2half_rn(A[(size_t)r * K + k])
                                 : __float2half_rn(0.f);
    }
}

// Prep 3: B panel [n][K_pad] fp16 at bOff via smem transpose.
// Block: 64 n x 32 k.  grid = (NVP/64, K_pad/32).
__global__ __launch_bounds__(256) void prep_b_kernel(
    const float* __restrict__ RF, int K, int K_pad, size_t bOff)
{
    __shared__ float s[64][33];
    int t  = threadIdx.x;
    int n0 = blockIdx.x * 64;
    int k0 = blockIdx.y * 32;

    int n_l = t & 63;
    int kq  = t >> 6;
    int n   = n0 + n_l;
    int idx = (n < NV) ? g_idx32[n] : 0;
    #pragma unroll
    for (int p = 0; p < 8; p++) {
        int k_l = p * 4 + kq;
        int k   = k0 + k_l;
        float v = 0.f;
        if (k < K && n < NV) {
            float x = RF[(size_t)k * NVT + idx];
            v = (x > 0.f) ? x : 0.01f * x;
        }
        s[n_l][k_l] = v;
    }
    __syncthreads();

    int nr = t >> 2;
    int q  = t & 3;
    __half h[8];
    #pragma unroll
    for (int i = 0; i < 8; i++) h[i] = __float2half_rn(s[nr][q * 8 + i]);
    *(uint4*)&g_Bh[bOff + (size_t)(n0 + nr) * K_pad + k0 + q * 8] = *(uint4*)h;
}

// ---------------------------------------------------------------------------
// FP16 GEMM (f32 accumulate), BK=64, 3-stage cp.async, ldmatrix fragments,
// w-scale epilogue. Panels at aOff/bOff. Exact R10/R13 mainloop.
// block = 256 (8 warps: 2M x 4N, warp tile 64x32); grid = (M/128, 63).
// ---------------------------------------------------------------------------
__global__ __launch_bounds__(NTHREADS, 2) void gemm_fp16_kernel(
    float* __restrict__ out, int K_pad, int cShift, int off, int aOff, size_t bOff)
{
    extern __shared__ __align__(128) char smem[];
    const uint32_t smb = smem_u32(smem);

    const int tid  = threadIdx.x;
    const int m0   = blockIdx.x * BM;
    const int n0   = blockIdx.y * BN;
    const int lane = tid & 31;
    const int warp = tid >> 5;
    const int g    = lane >> 2;
    const int t    = lane & 3;
    const int warpM = warp >> 2;
    const int warpN = warp & 3;
    const int niter = K_pad / BK;

    const __half* __restrict__ Ap = g_Ah + aOff;
    const __half* __restrict__ Bp = g_Bh + bOff;

    float acc[4][4][4];
    #pragma unroll
    for (int i = 0; i < 4; i++)
        #pragma unroll
        for (int j = 0; j < 4; j++)
            #pragma unroll
            for (int r = 0; r < 4; r++) acc[i][j][r] = 0.f;

    auto issue = [&](int j) {
        uint32_t Ab = smb + (j % NSTG) * STG_BYTES;
        uint32_t Bb = Ab + A_ST;
        int k0 = j * BK;
        #pragma unroll
        for (int u = 0; u < 4; u++) {
            int e = tid + NTHREADS * u;
            int r = e >> 3, ck = e & 7;
            const __half* srcA = Ap + (size_t)(m0 + r) * K_pad + k0 + ck * 8;
            asm volatile("cp.async.cg.shared.global [%0], [%1], 16;"
                         :: "r"(Ab + SWB(r, ck)), "l"(srcA));
            const __half* srcB = Bp + (size_t)(n0 + r) * K_pad + k0 + ck * 8;
            asm volatile("cp.async.cg.shared.global [%0], [%1], 16;"
                         :: "r"(Bb + SWB(r, ck)), "l"(srcB));
        }
    };

    #pragma unroll
    for (int p = 0; p < NSTG - 1; p++) {
        if (p < niter) issue(p);
        asm volatile("cp.async.commit_group;");
    }

    const int la_row8 = (lane & 7) + ((lane >> 3) & 1) * 8;
    const int la_ckhi = lane >> 4;
    const int lb_row  = (lane & 7) + ((lane >> 4) << 3);
    const int lb_ck   = (lane >> 3) & 1;

    for (int i = 0; i < niter; i++) {
        asm volatile("cp.async.wait_group %0;" :: "n"(NSTG - 2));
        __syncthreads();
        if (i + NSTG - 1 < niter) issue(i + NSTG - 1);
        asm volatile("cp.async.commit_group;");

        uint32_t As = smb + (i % NSTG) * STG_BYTES;
        uint32_t Bs = As + A_ST;

        #pragma unroll
        for (int s = 0; s < 4; s++) {
            uint32_t a[4][4];
            #pragma unroll
            for (int mf = 0; mf < 4; mf++) {
                int row = warpM * 64 + mf * 16 + la_row8;
                int ck  = s * 2 + la_ckhi;
                uint32_t ad = As + SWB(row, ck);
                asm volatile("ldmatrix.sync.aligned.m8n8.x4.shared.b16 "
                             "{%0,%1,%2,%3}, [%4];"
                             : "=r"(a[mf][0]), "=r"(a[mf][1]),
                               "=r"(a[mf][2]), "=r"(a[mf][3]) : "r"(ad));
            }
            uint32_t b[4][2];
            #pragma unroll
            for (int nfp = 0; nfp < 2; nfp++) {
                int row = warpN * 32 + nfp * 16 + lb_row;
                int ck  = s * 2 + lb_ck;
                uint32_t bd = Bs + SWB(row, ck);
                uint32_t r0, r1, r2, r3;
                asm volatile("ldmatrix.sync.aligned.m8n8.x4.shared.b16 "
                             "{%0,%1,%2,%3}, [%4];"
                             : "=r"(r0), "=r"(r1), "=r"(r2), "=r"(r3) : "r"(bd));
                b[nfp * 2 + 0][0] = r0; b[nfp * 2 + 0][1] = r1;
                b[nfp * 2 + 1][0] = r2; b[nfp * 2 + 1][1] = r3;
            }
            #pragma unroll
            for (int mf = 0; mf < 4; mf++)
                #pragma unroll
                for (int nf = 0; nf < 4; nf++) {
                    asm volatile(
                        "mma.sync.aligned.m16n8k16.row.col.f32.f16.f16.f32 "
                        "{%0,%1,%2,%3}, {%4,%5,%6,%7}, {%8,%9}, {%0,%1,%2,%3};"
                        : "+f"(acc[mf][nf][0]), "+f"(acc[mf][nf][1]),
                          "+f"(acc[mf][nf][2]), "+f"(acc[mf][nf][3])
                        : "r"(a[mf][0]), "r"(a[mf][1]), "r"(a[mf][2]), "r"(a[mf][3]),
                          "r"(b[nf][0]), "r"(b[nf][1]));
                }
        }
        __syncthreads();
    }

    const int cMask = (1 << cShift) - 1;
    #pragma unroll
    for (int mf = 0; mf < 4; mf++) {
        #pragma unroll
        for (int half = 0; half < 2; half++) {
            int m   = m0 + warpM * 64 + mf * 16 + g + half * 8;
            int c   = m & cMask;
            int bI  = m >> cShift;
            const float* wrow = g_wsel + (size_t)(off + c) * NV;
            float* orow = out + ((size_t)bI * CSUM + off + c) * NV;
            #pragma unroll
            for (int nf = 0; nf < 4; nf++) {
                int n = n0 + warpN * 32 + nf * 8 + t * 2;
                if (n < NV) {
                    float2 wv = *(const float2*)(wrow + n);
                    float2 res;
                    res.x = acc[mf][nf][half * 2 + 0] * wv.x;
                    res.y = acc[mf][nf][half * 2 + 1] * wv.y;
                    *(float2*)(orow + n) = res;
                }
            }
        }
    }
}

// ---------------------------------------------------------------------------
// Streams + events, created once pre-main. Fallback: fully sequential.
// ---------------------------------------------------------------------------
struct OverlapCtx {
    cudaStream_t s1 = nullptr, s2 = nullptr;
    cudaEvent_t evI = nullptr, evW = nullptr;
    cudaEvent_t evB[4] = {nullptr, nullptr, nullptr, nullptr};
    cudaEvent_t evA[4] = {nullptr, nullptr, nullptr, nullptr};
    bool ok = false;
    OverlapCtx() {
        bool o = (cudaStreamCreateWithFlags(&s1, cudaStreamNonBlocking) == cudaSuccess)
              && (cudaStreamCreateWithFlags(&s2, cudaStreamNonBlocking) == cudaSuccess)
              && (cudaEventCreateWithFlags(&evI, cudaEventDisableTiming) == cudaSuccess)
              && (cudaEventCreateWithFlags(&evW, cudaEventDisableTiming) == cudaSuccess);
        for (int i = 0; i < 4 && o; i++)
            o = (cudaEventCreateWithFlags(&evB[i], cudaEventDisableTiming) == cudaSuccess)
             && (cudaEventCreateWithFlags(&evA[i], cudaEventDisableTiming) == cudaSuccess);
        ok = o;
    }
};
static OverlapCtx g_ctx;

// ---------------------------------------------------------------------------
extern "C" void kernel_launch(void* const* d_in, const int* in_sizes, int n_in,
                              void* d_out, int out_size)
{
    static const int fsz[4] = {1605632,  802816,  401408,  200704};
    static const int rsz[4] = {62720000, 15680000, 3920000, 980000};
    static const int wsz[4] = {1280000,  2560000,  5120000, 10240000};

    const float* F[4]  = {nullptr, nullptr, nullptr, nullptr};
    const float* RF[4] = {nullptr, nullptr, nullptr, nullptr};
    const float* W[4]  = {nullptr, nullptr, nullptr, nullptr};
    const void* roi = nullptr;

    for (int i = 0; i < n_in; i++) {
        int s = in_sizes[i];
        if (s == NV) { roi = d_in[i]; continue; }
        for (int j = 0; j < 4; j++) {
            if (s == fsz[j]) F[j]  = (const float*)d_in[i];
            if (s == rsz[j]) RF[j] = (const float*)d_in[i];
            if (s == wsz[j]) W[j]  = (const float*)d_in[i];
        }
    }

    float* out = (float*)d_out;

    static bool attr_set = false;
    if (!attr_set) {
        cudaFuncSetAttribute(gemm_fp16_kernel,
                             cudaFuncAttributeMaxDynamicSharedMemorySize, SMEM_BYTES);
        attr_set = true;
    }

    static const int Cs[4]    = {64, 128, 256, 512};
    static const int cSh[4]   = {6, 7, 8, 9};
    static const int Ks[4]    = {3136, 784, 196, 49};
    static const int Kpads[4] = {3136, 832, 256, 64};
    static const int offs[4]  = {0, 64, 192, 448};
    static const int aOff[4]  = {0, 512*3136, 512*3136 + 1024*832,
                                 512*3136 + 1024*832 + 2048*256};
    static const size_t bOff[4] = {0, (size_t)NVP*3136, (size_t)NVP*(3136+832),
                                   (size_t)NVP*(3136+832+256)};

    auto prepA = [&](int l, cudaStream_t st) {
        int M = BATCH * Cs[l];
        prep_a_kernel<<<(M * Kpads[l] + 1023) / 1024, 256, 0, st>>>(
            F[l], M, Ks[l], Kpads[l], aOff[l]);
    };
    auto prepB = [&](int l, cudaStream_t st) {
        prep_b_kernel<<<dim3(NVP / 64, Kpads[l] / 32), 256, 0, st>>>(
            RF[l], Ks[l], Kpads[l], bOff[l]);
    };
    auto gemm = [&](int l) {
        int M = BATCH * Cs[l];
        dim3 grid(M / BM, NVP / BN);
        gemm_fp16_kernel<<<grid, NTHREADS, SMEM_BYTES>>>(
            out, Kpads[l], cSh[l], offs[l], aOff[l], bOff[l]);
    };

    if (g_ctx.ok) {
        // s0: idx, then gemms in order 3,2,1,0 (small layers first so the big
        // layer-0 B gather on s1 overlaps gemm3/2/1 at full grid sizes).
        prep_idx_kernel<<<32, 256>>>(roi);
        cudaEventRecord(g_ctx.evI, 0);
        cudaStreamWaitEvent(g_ctx.s1, g_ctx.evI, 0);
        cudaStreamWaitEvent(g_ctx.s2, g_ctx.evI, 0);

        // s1: B panels, small layers first, big layer-0 last (overlaps gemms)
        for (int l = 3; l >= 0; l--) {
            prepB(l, g_ctx.s1);
            cudaEventRecord(g_ctx.evB[l], g_ctx.s1);
        }

        // s2: w gather + A panels (all tiny; done within ~25us)
        prep_w_kernel<<<dim3(32, 240), 256, 0, g_ctx.s2>>>(W[0], W[1], W[2], W[3]);
        cudaEventRecord(g_ctx.evW, g_ctx.s2);
        for (int l = 3; l >= 0; l--) {
            prepA(l, g_ctx.s2);
            cudaEventRecord(g_ctx.evA[l], g_ctx.s2);
        }

        // s0: gemm chain 3,2,1,0
        cudaStreamWaitEvent(0, g_ctx.evW, 0);
        for (int l = 3; l >= 0; l--) {
            cudaStreamWaitEvent(0, g_ctx.evB[l], 0);
            cudaStreamWaitEvent(0, g_ctx.evA[l], 0);
            gemm(l);
        }
    } else {
        prep_idx_kernel<<<32, 256>>>(roi);
        prep_w_kernel<<<dim3(32, 240), 256>>>(W[0], W[1], W[2], W[3]);
        for (int l = 0; l < 4; l++) {
            prepA(l, 0);
            prepB(l, 0);
            gemm(l);
        }
    }
}